// round 4
// baseline (speedup 1.0000x reference)
#include <cuda_runtime.h>
#include <cuda_bf16.h>

// ---------------------------------------------------------------------------
// Problem constants
// ---------------------------------------------------------------------------
#define BB 128
#define JJ 8192
#define DD 32
#define HH 128

#define TJ 64       // cells per CTA in main kernel
#define NT 256      // threads per CTA

// ---------------------------------------------------------------------------
// Scratch (device globals; no allocations allowed)
// ---------------------------------------------------------------------------
__device__ float g_fej[JJ * HH];          // fe @ h_w1[1:] + h_b1   (4 MB)
__device__ float g_num[BB * 4 * DD];      // sum_j e_{jw} * h_out_{jd}
__device__ float g_sumexp[BB * 4];        // sum_j e_{jw}
__device__ int   g_maskcnt[BB];           // # observed junctions per batch

// ---------------------------------------------------------------------------
// Shared-memory layout (offsets in floats)
//   h1s [64][132]  -- dead after GEMM; overlaid by ELOG/NUMS/SUME/MCNT
//   w2t [32][132]  -- h_w2 transposed [d][k]
//   hout[64][36]
// ---------------------------------------------------------------------------
#define OFF_H1S   0
#define OFF_ELOG  0                        // overlay (64 cells * 4 heads)
#define OFF_NUMS  256                      // overlay [4][32]
#define OFF_SUME  384                      // overlay [4]
#define OFF_MCNT  388                      // overlay (int)
#define OFF_W2T   8448                     // 32*132 = 4224
#define OFF_HOUT  12672                    // 64*36  = 2304
#define OFF_W10   14976                    // 128
#define OFF_LN1W  15104                    // 128
#define OFF_LN1B  15232                    // 128
#define OFF_LN2W  15360                    // 32
#define OFF_LN2B  15392                    // 32
#define OFF_HB2   15424                    // 32
#define OFF_GW1   15456                    // [32][16] = 512
#define OFF_GB1   15968                    // 16
#define OFF_GW2   16048 - 64               // 15984: [16][4] = 64
#define OFF_GB2   16048                    // 4
#define OFF_XS    16052                    // 64
#define OFF_MS    16116                    // 64 ints
#define SMEM_FLOATS 16180
#define SMEM_BYTES  (SMEM_FLOATS * 4)      // 64720 B

// packed fp32x2 FMA:  c = a*b + c   (two independent FMAs per instruction)
#define FMA2(c_, a_, b_) \
    asm("fma.rn.f32x2 %0, %1, %2, %0;" : "+l"(c_) : "l"(a_), "l"(b_))

// ---------------------------------------------------------------------------
// Kernel Z: zero per-launch global accumulators
// ---------------------------------------------------------------------------
__global__ void k_zero() {
    int i = blockIdx.x * 256 + threadIdx.x;
    if (i < BB * 4 * DD) g_num[i] = 0.f;
    if (i < BB * 4)      g_sumexp[i] = 0.f;
    if (i < BB)          g_maskcnt[i] = 0;
}

// ---------------------------------------------------------------------------
// Kernel A: fej[j][h] = h_b1[h] + sum_d fe[j][d] * h_w1[1+d][h]
// ---------------------------------------------------------------------------
__global__ void k_fej(const float* __restrict__ fe,
                      const float* __restrict__ h_w1,
                      const float* __restrict__ h_b1) {
    __shared__ float fes[DD];
    const int j = blockIdx.x;
    const int t = threadIdx.x;           // 128 threads = H
    if (t < DD) fes[t] = fe[j * DD + t];
    __syncthreads();
    float acc = h_b1[t];
#pragma unroll
    for (int d = 0; d < DD; d++)
        acc = fmaf(fes[d], h_w1[(1 + d) * HH + t], acc);
    g_fej[j * HH + t] = acc;
}

// ---------------------------------------------------------------------------
// Kernel B: fused per-cell pipeline, 64 cells per CTA
//   thread (c,q): c = t>>2 (cell), q = t&3 (quarter)
// ---------------------------------------------------------------------------
__global__ void __launch_bounds__(NT, 3)
k_main(const float* __restrict__ x, const int* __restrict__ mask,
       const float* __restrict__ h_w1,
       const float* __restrict__ h_ln1_w, const float* __restrict__ h_ln1_b,
       const float* __restrict__ h_w2,   const float* __restrict__ h_b2,
       const float* __restrict__ h_ln2_w, const float* __restrict__ h_ln2_b,
       const float* __restrict__ gw1,    const float* __restrict__ gb1,
       const float* __restrict__ gw2,    const float* __restrict__ gb2) {
    extern __shared__ float sm[];
    int* smi = (int*)sm;
    const int t  = threadIdx.x;
    const int b  = blockIdx.y;
    const int j0 = blockIdx.x * TJ;
    const int c = t >> 2, q = t & 3;
    const int w = t >> 5, lane = t & 31;

    // ---- phase 0: stage weights / inputs ----
    for (int i = t; i < HH * DD; i += NT) {           // h_w2 -> transposed [d][132]
        int k = i >> 5, d = i & 31;
        sm[OFF_W2T + d * 132 + k] = h_w2[i];
    }
    if (t < HH) {
        sm[OFF_W10 + t]  = h_w1[t];
        sm[OFF_LN1W + t] = h_ln1_w[t];
        sm[OFF_LN1B + t] = h_ln1_b[t];
    }
    if (t < DD) {
        sm[OFF_LN2W + t] = h_ln2_w[t];
        sm[OFF_LN2B + t] = h_ln2_b[t];
        sm[OFF_HB2 + t]  = h_b2[t];
    }
    for (int i = t; i < 512; i += NT) sm[OFF_GW1 + i] = gw1[i];
    if (t < 16) sm[OFF_GB1 + t] = gb1[t];
    if (t < 64) sm[OFF_GW2 + t] = gw2[t];
    if (t < 4)  sm[OFF_GB2 + t] = gb2[t];
    if (t < TJ) {
        sm[OFF_XS + t]  = x[b * JJ + j0 + t];
        smi[OFF_MS + t] = mask[b * JJ + j0 + t];
    }
    __syncthreads();

    // ---- phase 1: pre = x*w1_0 + fej ; LN(128) ; relu -> h1s[c][k] ----
    {
        const float4* fj = reinterpret_cast<const float4*>(g_fej + (j0 + c) * HH + q * 32);
        const float xv = sm[OFF_XS + c];
        float4 pv[8];
        float s = 0.f, ss = 0.f;
#pragma unroll
        for (int i = 0; i < 8; i++) {
            float4 f = fj[i];
            const float4 wv = *reinterpret_cast<const float4*>(&sm[OFF_W10 + q * 32 + 4 * i]);
            float4 v;
            v.x = fmaf(xv, wv.x, f.x);
            v.y = fmaf(xv, wv.y, f.y);
            v.z = fmaf(xv, wv.z, f.z);
            v.w = fmaf(xv, wv.w, f.w);
            pv[i] = v;
            s  += (v.x + v.y) + (v.z + v.w);
            ss += v.x * v.x + v.y * v.y + v.z * v.z + v.w * v.w;
        }
        s  += __shfl_xor_sync(0xffffffffu, s, 1);
        s  += __shfl_xor_sync(0xffffffffu, s, 2);
        ss += __shfl_xor_sync(0xffffffffu, ss, 1);
        ss += __shfl_xor_sync(0xffffffffu, ss, 2);
        const float mean = s * (1.f / 128.f);
        const float var  = ss * (1.f / 128.f) - mean * mean;
        const float rstd = rsqrtf(var + 1e-5f);
#pragma unroll
        for (int i = 0; i < 8; i++) {
            float4 v = pv[i];
            const float4 lw = *reinterpret_cast<const float4*>(&sm[OFF_LN1W + q * 32 + 4 * i]);
            const float4 lb = *reinterpret_cast<const float4*>(&sm[OFF_LN1B + q * 32 + 4 * i]);
            float4 o;
            o.x = fmaxf(0.f, fmaf((v.x - mean) * rstd, lw.x, lb.x));
            o.y = fmaxf(0.f, fmaf((v.y - mean) * rstd, lw.y, lb.y));
            o.z = fmaxf(0.f, fmaf((v.z - mean) * rstd, lw.z, lb.z));
            o.w = fmaxf(0.f, fmaf((v.w - mean) * rstd, lw.w, lb.w));
            *reinterpret_cast<float4*>(&sm[OFF_H1S + c * 132 + q * 32 + 4 * i]) = o;
        }
    }
    __syncwarp();   // h1s rows of this warp's 8 cells consumed by same warp

    // ---- phase 2: GEMM. thread (c,q) computes acc[d] for d in [8q,8q+8),
    //      all K=128, packed 2 k's per fma.rn.f32x2. k order rotated by 8q
    //      so the 4 q-lanes hit distinct banks on the w2t loads. ----
    float hv[8];
    {
        const float* h1row = &sm[OFF_H1S + c * 132];
        const float* wbase = &sm[OFF_W2T + (8 * q) * 132];
        unsigned long long acc[8] = {0ull,0ull,0ull,0ull,0ull,0ull,0ull,0ull};
        int kr = 8 * q;
#pragma unroll 4
        for (int it = 0; it < 32; it++) {
            const ulonglong2 a = *reinterpret_cast<const ulonglong2*>(h1row + kr);
#pragma unroll
            for (int dd = 0; dd < 8; dd++) {
                const ulonglong2 wv = *reinterpret_cast<const ulonglong2*>(wbase + dd * 132 + kr);
                FMA2(acc[dd], a.x, wv.x);
                FMA2(acc[dd], a.y, wv.y);
            }
            kr = (kr + 4) & 127;
        }
#pragma unroll
        for (int dd = 0; dd < 8; dd++) {
            unsigned lo, hi;
            asm("mov.b64 {%0,%1}, %2;" : "=r"(lo), "=r"(hi) : "l"(acc[dd]));
            hv[dd] = __uint_as_float(lo) + __uint_as_float(hi);
        }
    }

    __syncthreads();                       // all warps done with h1s
    // zero overlay accumulators (region reuses h1s)
    if (t < 128) sm[OFF_NUMS + t] = 0.f;
    if (t < 4)   sm[OFF_SUME + t] = 0.f;
    if (t == 0)  smi[OFF_MCNT] = 0;

    // ---- phase 3: + h_b2, LN over D=32 (4-lane shfl), relu -> hout ----
    {
        const float4 ba = *reinterpret_cast<const float4*>(&sm[OFF_HB2 + 8 * q]);
        const float4 bb = *reinterpret_cast<const float4*>(&sm[OFF_HB2 + 8 * q + 4]);
        float v[8];
        v[0] = hv[0] + ba.x; v[1] = hv[1] + ba.y; v[2] = hv[2] + ba.z; v[3] = hv[3] + ba.w;
        v[4] = hv[4] + bb.x; v[5] = hv[5] + bb.y; v[6] = hv[6] + bb.z; v[7] = hv[7] + bb.w;
        float s1 = 0.f, s2 = 0.f;
#pragma unroll
        for (int dd = 0; dd < 8; dd++) { s1 += v[dd]; s2 = fmaf(v[dd], v[dd], s2); }
        s1 += __shfl_xor_sync(0xffffffffu, s1, 1);
        s1 += __shfl_xor_sync(0xffffffffu, s1, 2);
        s2 += __shfl_xor_sync(0xffffffffu, s2, 1);
        s2 += __shfl_xor_sync(0xffffffffu, s2, 2);
        const float mean = s1 * (1.f / 32.f);
        const float var  = s2 * (1.f / 32.f) - mean * mean;
        const float rstd = rsqrtf(var + 1e-5f);
        const float4 lwa = *reinterpret_cast<const float4*>(&sm[OFF_LN2W + 8 * q]);
        const float4 lwb = *reinterpret_cast<const float4*>(&sm[OFF_LN2W + 8 * q + 4]);
        const float4 lba = *reinterpret_cast<const float4*>(&sm[OFF_LN2B + 8 * q]);
        const float4 lbb = *reinterpret_cast<const float4*>(&sm[OFF_LN2B + 8 * q + 4]);
        float4 o1, o2;
        o1.x = fmaxf(0.f, fmaf((v[0] - mean) * rstd, lwa.x, lba.x));
        o1.y = fmaxf(0.f, fmaf((v[1] - mean) * rstd, lwa.y, lba.y));
        o1.z = fmaxf(0.f, fmaf((v[2] - mean) * rstd, lwa.z, lba.z));
        o1.w = fmaxf(0.f, fmaf((v[3] - mean) * rstd, lwa.w, lba.w));
        o2.x = fmaxf(0.f, fmaf((v[4] - mean) * rstd, lwb.x, lbb.x));
        o2.y = fmaxf(0.f, fmaf((v[5] - mean) * rstd, lwb.y, lbb.y));
        o2.z = fmaxf(0.f, fmaf((v[6] - mean) * rstd, lwb.z, lbb.z));
        o2.w = fmaxf(0.f, fmaf((v[7] - mean) * rstd, lwb.w, lbb.w));
        *reinterpret_cast<float4*>(&sm[OFF_HOUT + c * 36 + 8 * q])     = o1;
        *reinterpret_cast<float4*>(&sm[OFF_HOUT + c * 36 + 8 * q + 4]) = o2;
    }
    __syncthreads();                       // hout + overlay zeros visible

    // ---- phase 4: gate MLP -> logits -> clip -> mask -> exp (into ELOG) ----
    {
        const float* hrow = &sm[OFF_HOUT + c * 36];
        float g1v[4];
#pragma unroll
        for (int e = 0; e < 4; e++) g1v[e] = sm[OFF_GB1 + 4 * q + e];
#pragma unroll
        for (int d = 0; d < 32; d++) {
            const float hvv = hrow[d];
            const float4 gw = *reinterpret_cast<const float4*>(&sm[OFF_GW1 + d * 16 + 4 * q]);
            g1v[0] = fmaf(hvv, gw.x, g1v[0]);
            g1v[1] = fmaf(hvv, gw.y, g1v[1]);
            g1v[2] = fmaf(hvv, gw.z, g1v[2]);
            g1v[3] = fmaf(hvv, gw.w, g1v[3]);
        }
        float pl[4] = {0.f, 0.f, 0.f, 0.f};
#pragma unroll
        for (int e = 0; e < 4; e++) {
            const float gv = fmaxf(0.f, g1v[e]);
            const float4 g2 = *reinterpret_cast<const float4*>(&sm[OFF_GW2 + (4 * q + e) * 4]);
            pl[0] = fmaf(gv, g2.x, pl[0]);
            pl[1] = fmaf(gv, g2.y, pl[1]);
            pl[2] = fmaf(gv, g2.z, pl[2]);
            pl[3] = fmaf(gv, g2.w, pl[3]);
        }
#pragma unroll
        for (int k = 0; k < 4; k++) {
            pl[k] += __shfl_xor_sync(0xffffffffu, pl[k], 1);
            pl[k] += __shfl_xor_sync(0xffffffffu, pl[k], 2);
        }
        const int mval = smi[OFF_MS + c];
        const float raw = pl[q] + sm[OFF_GB2 + q];
        const float lgt = fminf(10.f, fmaxf(-10.f, raw));
        const float ev  = (mval > 0) ? __expf(lgt) : 0.f;
        sm[OFF_ELOG + c * 4 + q] = ev;
        float se = ev;
        se += __shfl_xor_sync(0xffffffffu, se, 4);
        se += __shfl_xor_sync(0xffffffffu, se, 8);
        se += __shfl_xor_sync(0xffffffffu, se, 16);
        if (lane < 4) atomicAdd(&sm[OFF_SUME + lane], se);
        const unsigned bal = __ballot_sync(0xffffffffu, (q == 0) && (mval > 0));
        if (lane == 0) atomicAdd(&smi[OFF_MCNT], (int)__popc(bal));
    }
    __syncwarp();

    // ---- phase 5: pooling partials. thread (w,lane): rows 8w..8w+7, d=lane ----
    {
        const int r0 = w * 8;
        float p0 = 0.f, p1 = 0.f, p2 = 0.f, p3 = 0.f;
#pragma unroll
        for (int rr = 0; rr < 8; rr++) {
            const float4 ev = *reinterpret_cast<const float4*>(&sm[OFF_ELOG + (r0 + rr) * 4]);
            const float h = sm[OFF_HOUT + (r0 + rr) * 36 + lane];
            p0 = fmaf(ev.x, h, p0);
            p1 = fmaf(ev.y, h, p1);
            p2 = fmaf(ev.z, h, p2);
            p3 = fmaf(ev.w, h, p3);
        }
        atomicAdd(&sm[OFF_NUMS + 0 * 32 + lane], p0);
        atomicAdd(&sm[OFF_NUMS + 1 * 32 + lane], p1);
        atomicAdd(&sm[OFF_NUMS + 2 * 32 + lane], p2);
        atomicAdd(&sm[OFF_NUMS + 3 * 32 + lane], p3);
    }
    __syncthreads();

    // ---- phase 6: flush tile accumulators ----
    if (t < 128)       atomicAdd(&g_num[b * 128 + t], sm[OFF_NUMS + t]);
    else if (t < 132)  atomicAdd(&g_sumexp[b * 4 + (t - 128)], sm[OFF_SUME + (t - 128)]);
    else if (t == 132) atomicAdd(&g_maskcnt[b], smi[OFF_MCNT]);
}

// ---------------------------------------------------------------------------
// Kernel C: per-batch tail  head_sums -> comb -> e1 -> e2 -> (mu, logvar)
// ---------------------------------------------------------------------------
__global__ void k_tail(const float* __restrict__ c_w,    const float* __restrict__ c_b,
                       const float* __restrict__ c_ln_w, const float* __restrict__ c_ln_b,
                       const float* __restrict__ e_w1,   const float* __restrict__ e_b1,
                       const float* __restrict__ e_ln1_w, const float* __restrict__ e_ln1_b,
                       const float* __restrict__ e_w2,   const float* __restrict__ e_b2,
                       const float* __restrict__ e_ln2_w, const float* __restrict__ e_ln2_b,
                       float* __restrict__ out) {
    const int b = blockIdx.x;
    const int t = threadIdx.x;      // 256
    __shared__ float hs[128];
    __shared__ float comb[32];
    __shared__ float h2s[256];
    __shared__ float red[16];
    __shared__ float part[256];

    const int mc = g_maskcnt[b];
    if (t < 128) {
        const float den = g_sumexp[b * 4 + (t >> 5)];
        hs[t] = (mc > 0) ? g_num[b * 128 + t] / den : 0.f;
    }
    __syncthreads();

    // comb = relu(LN(hs @ c_w + c_b)); split K=128 across 8 groups
    {
        const int o = t & 31, kg = t >> 5;
        float a = 0.f;
#pragma unroll
        for (int k = 0; k < 16; k++)
            a = fmaf(hs[kg * 16 + k], c_w[(kg * 16 + k) * 32 + o], a);
        part[kg * 32 + o] = a;
    }
    __syncthreads();
    if (t < 32) {
        float a = c_b[t];
#pragma unroll
        for (int g = 0; g < 8; g++) a += part[g * 32 + t];
        float s1 = a, s2 = a * a;
#pragma unroll
        for (int m = 16; m > 0; m >>= 1) {
            s1 += __shfl_xor_sync(0xffffffffu, s1, m);
            s2 += __shfl_xor_sync(0xffffffffu, s2, m);
        }
        const float mean = s1 * (1.f / 32.f);
        const float var  = s2 * (1.f / 32.f) - mean * mean;
        const float r = rsqrtf(var + 1e-5f);
        const float v = fmaxf(0.f, fmaf((a - mean) * r, c_ln_w[t], c_ln_b[t]));
        comb[t] = (mc > 0) ? v : 0.f;
    }
    __syncthreads();

    // h = relu(LN(comb @ e_w1 + e_b1))   (256-wide block LN)
    {
        float a = e_b1[t];
#pragma unroll
        for (int k = 0; k < 32; k++) a = fmaf(comb[k], e_w1[k * 256 + t], a);
        float s1 = a, s2 = a * a;
#pragma unroll
        for (int m = 16; m > 0; m >>= 1) {
            s1 += __shfl_xor_sync(0xffffffffu, s1, m);
            s2 += __shfl_xor_sync(0xffffffffu, s2, m);
        }
        if ((t & 31) == 0) { red[t >> 5] = s1; red[8 + (t >> 5)] = s2; }
        __syncthreads();
        float S = 0.f, SS = 0.f;
#pragma unroll
        for (int i = 0; i < 8; i++) { S += red[i]; SS += red[8 + i]; }
        const float mean = S * (1.f / 256.f);
        const float var  = SS * (1.f / 256.f) - mean * mean;
        const float r = rsqrtf(var + 1e-5f);
        h2s[t] = fmaxf(0.f, fmaf((a - mean) * r, e_ln1_w[t], e_ln1_b[t]));
    }
    __syncthreads();

    // o = relu(LN(h @ e_w2 + e_b2)); split K=256 across 4 groups
    {
        const int o = t & 63, kg = t >> 6;
        float a = 0.f;
#pragma unroll 8
        for (int k = 0; k < 64; k++)
            a = fmaf(h2s[kg * 64 + k], e_w2[(kg * 64 + k) * 64 + o], a);
        part[kg * 64 + o] = a;
    }
    __syncthreads();
    float oacc = 0.f;
    if (t < 64) {
        oacc = e_b2[t] + part[t] + part[64 + t] + part[128 + t] + part[192 + t];
        float s1 = oacc, s2 = oacc * oacc;
#pragma unroll
        for (int m = 16; m > 0; m >>= 1) {
            s1 += __shfl_xor_sync(0xffffffffu, s1, m);
            s2 += __shfl_xor_sync(0xffffffffu, s2, m);
        }
        if ((t & 31) == 0) { red[t >> 5] = s1; red[8 + (t >> 5)] = s2; }
    }
    __syncthreads();
    if (t < 64) {
        const float S  = red[0] + red[1];
        const float SS = red[8] + red[9];
        const float mean = S * (1.f / 64.f);
        const float var  = SS * (1.f / 64.f) - mean * mean;
        const float r = rsqrtf(var + 1e-5f);
        const float o = fmaxf(0.f, fmaf((oacc - mean) * r, e_ln2_w[t], e_ln2_b[t]));
        out[(t >> 5) * (BB * 32) + b * 32 + (t & 31)] = o;
    }
}

// ---------------------------------------------------------------------------
// Launch
// ---------------------------------------------------------------------------
extern "C" void kernel_launch(void* const* d_in, const int* in_sizes, int n_in,
                              void* d_out, int out_size) {
    const float* x       = (const float*)d_in[0];
    const int*   mask    = (const int*)  d_in[1];
    const float* fe      = (const float*)d_in[2];
    const float* h_w1    = (const float*)d_in[3];
    const float* h_b1    = (const float*)d_in[4];
    const float* h_ln1_w = (const float*)d_in[5];
    const float* h_ln1_b = (const float*)d_in[6];
    const float* h_w2    = (const float*)d_in[7];
    const float* h_b2    = (const float*)d_in[8];
    const float* h_ln2_w = (const float*)d_in[9];
    const float* h_ln2_b = (const float*)d_in[10];
    const float* g_w1    = (const float*)d_in[11];
    const float* g_b1    = (const float*)d_in[12];
    const float* g_w2    = (const float*)d_in[13];
    const float* g_b2    = (const float*)d_in[14];
    const float* c_w     = (const float*)d_in[15];
    const float* c_b     = (const float*)d_in[16];
    const float* c_ln_w  = (const float*)d_in[17];
    const float* c_ln_b  = (const float*)d_in[18];
    const float* e_w1    = (const float*)d_in[19];
    const float* e_b1    = (const float*)d_in[20];
    const float* e_ln1_w = (const float*)d_in[21];
    const float* e_ln1_b = (const float*)d_in[22];
    const float* e_w2    = (const float*)d_in[23];
    const float* e_b2    = (const float*)d_in[24];
    const float* e_ln2_w = (const float*)d_in[25];
    const float* e_ln2_b = (const float*)d_in[26];
    float* out = (float*)d_out;

    cudaFuncSetAttribute(k_main, cudaFuncAttributeMaxDynamicSharedMemorySize, SMEM_BYTES);

    k_zero<<<64, 256>>>();
    k_fej<<<JJ, HH>>>(fe, h_w1, h_b1);
    dim3 grid(JJ / TJ, BB);
    k_main<<<grid, NT, SMEM_BYTES>>>(x, mask, h_w1, h_ln1_w, h_ln1_b,
                                     h_w2, h_b2, h_ln2_w, h_ln2_b,
                                     g_w1, g_b1, g_w2, g_b2);
    k_tail<<<BB, 256>>>(c_w, c_b, c_ln_w, c_ln_b,
                        e_w1, e_b1, e_ln1_w, e_ln1_b,
                        e_w2, e_b2, e_ln2_w, e_ln2_b, out);
}

// round 5
// speedup vs baseline: 1.3171x; 1.3171x over previous
#include <cuda_runtime.h>
#include <cuda_bf16.h>

// ---------------------------------------------------------------------------
// Problem constants
// ---------------------------------------------------------------------------
#define BB 128
#define JJ 8192
#define DD 32
#define HH 128

#define TJ 64       // cells per CTA in main kernel
#define NT 256      // threads per CTA

// ---------------------------------------------------------------------------
// Scratch (device globals; no allocations allowed)
// ---------------------------------------------------------------------------
__device__ float g_fej[JJ * HH];          // fe @ h_w1[1:] + h_b1   (4 MB)
__device__ float g_num[BB * 4 * DD];      // sum_j e_{jw} * h_out_{jd}
__device__ float g_sumexp[BB * 4];        // sum_j e_{jw}
__device__ int   g_maskcnt[BB];           // # observed junctions per batch

// ---------------------------------------------------------------------------
// Shared-memory layout (round-2 layout, offsets in floats)
// ---------------------------------------------------------------------------
#define OFF_H1S   0
#define OFF_W2T   (OFF_H1S + TJ*132)          // 8448
#define OFF_HOUT  (OFF_W2T + 32*132)          // 12672  [64][33]
#define OFF_W10   (OFF_HOUT + TJ*33)          // 14784
#define OFF_LN1W  (OFF_W10 + 128)             // 14912
#define OFF_LN1B  (OFF_LN1W + 128)            // 15040
#define OFF_LN2W  (OFF_LN1B + 128)            // 15168
#define OFF_LN2B  (OFF_LN2W + 32)             // 15200
#define OFF_HB2   (OFF_LN2B + 32)             // 15232
#define OFF_GW1   (OFF_HB2 + 32)              // 15264 : [32][16]
#define OFF_GB1   (OFF_GW1 + 512)             // 15776
#define OFF_GW2   (OFF_GB1 + 16)              // 15792 : [16][4]
#define OFF_GB2   (OFF_GW2 + 64)              // 15856
#define OFF_XS    (OFF_GB2 + 4)               // 15860
#define OFF_ELOG  (OFF_XS + 64)               // 15924 (16B aligned)
#define OFF_NUMS  (OFF_ELOG + 256)            // 16180 : [4][32]
#define OFF_SUME  (OFF_NUMS + 128)            // 16308
#define OFF_MS    (OFF_SUME + 4)              // 16312 (ints)
#define OFF_MCNT  (OFF_MS + 64)               // 16376 (int)
#define SMEM_BYTES 65536

// packed fp32x2 FMA:  c = a*b + c   (two independent FMAs per instruction)
#define FMA2(c_, a_, b_) \
    asm("fma.rn.f32x2 %0, %1, %2, %0;" : "+l"(c_) : "l"(a_), "l"(b_))

// ---------------------------------------------------------------------------
// Kernel Z: zero per-launch global accumulators
// ---------------------------------------------------------------------------
__global__ void k_zero() {
    int i = blockIdx.x * 256 + threadIdx.x;
    if (i < BB * 4 * DD) g_num[i] = 0.f;
    if (i < BB * 4)      g_sumexp[i] = 0.f;
    if (i < BB)          g_maskcnt[i] = 0;
}

// ---------------------------------------------------------------------------
// Kernel A: fej[j][h] = h_b1[h] + sum_d fe[j][d] * h_w1[1+d][h]
// ---------------------------------------------------------------------------
__global__ void k_fej(const float* __restrict__ fe,
                      const float* __restrict__ h_w1,
                      const float* __restrict__ h_b1) {
    __shared__ float fes[DD];
    const int j = blockIdx.x;
    const int t = threadIdx.x;           // 128 threads = H
    if (t < DD) fes[t] = fe[j * DD + t];
    __syncthreads();
    float acc = h_b1[t];
#pragma unroll
    for (int d = 0; d < DD; d++)
        acc = fmaf(fes[d], h_w1[(1 + d) * HH + t], acc);
    g_fej[j * HH + t] = acc;
}

// ---------------------------------------------------------------------------
// Kernel B: fused per-cell pipeline, 64 cells per CTA  (round-2 mapping)
// ---------------------------------------------------------------------------
__global__ void __launch_bounds__(NT, 3)
k_main(const float* __restrict__ x, const int* __restrict__ mask,
       const float* __restrict__ h_w1,
       const float* __restrict__ h_ln1_w, const float* __restrict__ h_ln1_b,
       const float* __restrict__ h_w2,   const float* __restrict__ h_b2,
       const float* __restrict__ h_ln2_w, const float* __restrict__ h_ln2_b,
       const float* __restrict__ gw1,    const float* __restrict__ gb1,
       const float* __restrict__ gw2,    const float* __restrict__ gb2) {
    extern __shared__ float sm[];
    int* smi = (int*)sm;
    const int t  = threadIdx.x;
    const int b  = blockIdx.y;
    const int j0 = blockIdx.x * TJ;
    const int c = t >> 2, q = t & 3;
    const int w = t >> 5, lane = t & 31, r0 = w * 8;

    // ---- phase 0: stage weights / inputs, zero tile accumulators ----
    if (t < 128) sm[OFF_NUMS + t] = 0.f;
    if (t < 4)   sm[OFF_SUME + t] = 0.f;
    if (t == 0)  smi[OFF_MCNT] = 0;
    for (int i = t; i < HH * DD; i += NT) {           // h_w2 -> transposed [d][132]
        int k = i >> 5, d = i & 31;
        sm[OFF_W2T + d * 132 + k] = h_w2[i];
    }
    if (t < HH) {
        sm[OFF_W10 + t]  = h_w1[t];
        sm[OFF_LN1W + t] = h_ln1_w[t];
        sm[OFF_LN1B + t] = h_ln1_b[t];
    }
    if (t < DD) {
        sm[OFF_LN2W + t] = h_ln2_w[t];
        sm[OFF_LN2B + t] = h_ln2_b[t];
        sm[OFF_HB2 + t]  = h_b2[t];
    }
    for (int i = t; i < 512; i += NT) sm[OFF_GW1 + i] = gw1[i];
    if (t < 16) sm[OFF_GB1 + t] = gb1[t];
    if (t < 64) sm[OFF_GW2 + t] = gw2[t];
    if (t < 4)  sm[OFF_GB2 + t] = gb2[t];
    if (t < TJ) {
        sm[OFF_XS + t]  = x[b * JJ + j0 + t];
        smi[OFF_MS + t] = mask[b * JJ + j0 + t];
    }
    __syncthreads();

    // ---- phase 1: pre = x*w1_0 + fej ; LN(128) ; relu ; -> h1s ----
    {
        const float4* fj = reinterpret_cast<const float4*>(g_fej + (j0 + c) * HH + q * 32);
        const float xv = sm[OFF_XS + c];
        float4 pv[8];
        float s = 0.f, ss = 0.f;
#pragma unroll
        for (int i = 0; i < 8; i++) {
            float4 f = fj[i];
            const float4 wv = *reinterpret_cast<const float4*>(&sm[OFF_W10 + q * 32 + 4 * i]);
            float4 v;
            v.x = fmaf(xv, wv.x, f.x);
            v.y = fmaf(xv, wv.y, f.y);
            v.z = fmaf(xv, wv.z, f.z);
            v.w = fmaf(xv, wv.w, f.w);
            pv[i] = v;
            s  += (v.x + v.y) + (v.z + v.w);
            ss += v.x * v.x + v.y * v.y + v.z * v.z + v.w * v.w;
        }
        s  += __shfl_xor_sync(0xffffffffu, s, 1);
        s  += __shfl_xor_sync(0xffffffffu, s, 2);
        ss += __shfl_xor_sync(0xffffffffu, ss, 1);
        ss += __shfl_xor_sync(0xffffffffu, ss, 2);
        const float mean = s * (1.f / 128.f);
        const float var  = ss * (1.f / 128.f) - mean * mean;
        const float rstd = rsqrtf(var + 1e-5f);
#pragma unroll
        for (int sstep = 0; sstep < 8; sstep++) {
            const int i = (sstep + 2 * q) & 7;   // rotation -> conflict-free STS.128
            float4 v = pv[i];
            const float4 lw = *reinterpret_cast<const float4*>(&sm[OFF_LN1W + q * 32 + 4 * i]);
            const float4 lb = *reinterpret_cast<const float4*>(&sm[OFF_LN1B + q * 32 + 4 * i]);
            float4 o;
            o.x = fmaxf(0.f, fmaf((v.x - mean) * rstd, lw.x, lb.x));
            o.y = fmaxf(0.f, fmaf((v.y - mean) * rstd, lw.y, lb.y));
            o.z = fmaxf(0.f, fmaf((v.z - mean) * rstd, lw.z, lb.z));
            o.w = fmaxf(0.f, fmaf((v.w - mean) * rstd, lw.w, lb.w));
            *reinterpret_cast<float4*>(&sm[OFF_H1S + c * 132 + q * 32 + 4 * i]) = o;
        }
    }
    __syncwarp();   // h1s rows 8w..8w+7 produced & consumed by warp w only

    // ---- phase 2: GEMM h1[64x128] @ w2[128x32], f32x2-packed along K.
    //      warp w: rows 8w..8w+7, lane = d. All offsets compile-time. ----
    float hv[8];
    {
        unsigned long long acc2[8] = {0ull,0ull,0ull,0ull,0ull,0ull,0ull,0ull};
        const float* wrow  = &sm[OFF_W2T + lane * 132];
        const float* h1base = &sm[OFF_H1S + r0 * 132];
#pragma unroll 4
        for (int k4 = 0; k4 < 32; k4++) {
            const ulonglong2 bv = *reinterpret_cast<const ulonglong2*>(wrow + 4 * k4);
#pragma unroll
            for (int rr = 0; rr < 8; rr++) {
                const ulonglong2 av = *reinterpret_cast<const ulonglong2*>(h1base + rr * 132 + 4 * k4);
                FMA2(acc2[rr], av.x, bv.x);
                FMA2(acc2[rr], av.y, bv.y);
            }
        }
#pragma unroll
        for (int rr = 0; rr < 8; rr++) {
            unsigned lo, hi;
            asm("mov.b64 {%0,%1}, %2;" : "=r"(lo), "=r"(hi) : "l"(acc2[rr]));
            hv[rr] = __uint_as_float(lo) + __uint_as_float(hi);
        }
    }

    // ---- phase 3a: store pre-LN rows (v = acc + b2) to hout ----
    {
        const float bb2 = sm[OFF_HB2 + lane];
#pragma unroll
        for (int rr = 0; rr < 8; rr++)
            sm[OFF_HOUT + (r0 + rr) * 33 + lane] = hv[rr] + bb2;
    }
    __syncwarp();

    // ---- phase 3b: LN over D=32 per row, 4-shfl variant.
    //      thread (c,q) handles row c, cols 8q..8q+8 (same warp as writer) ----
    {
        float v[8];
        float s1 = 0.f, s2 = 0.f;
#pragma unroll
        for (int i = 0; i < 8; i++) {
            v[i] = sm[OFF_HOUT + c * 33 + 8 * q + i];
            s1 += v[i];
            s2 = fmaf(v[i], v[i], s2);
        }
        s1 += __shfl_xor_sync(0xffffffffu, s1, 1);
        s1 += __shfl_xor_sync(0xffffffffu, s1, 2);
        s2 += __shfl_xor_sync(0xffffffffu, s2, 1);
        s2 += __shfl_xor_sync(0xffffffffu, s2, 2);
        const float mean = s1 * (1.f / 32.f);
        const float var  = s2 * (1.f / 32.f) - mean * mean;
        const float rstd = rsqrtf(var + 1e-5f);
        const float4 lwa = *reinterpret_cast<const float4*>(&sm[OFF_LN2W + 8 * q]);
        const float4 lwb = *reinterpret_cast<const float4*>(&sm[OFF_LN2W + 8 * q + 4]);
        const float4 lba = *reinterpret_cast<const float4*>(&sm[OFF_LN2B + 8 * q]);
        const float4 lbb = *reinterpret_cast<const float4*>(&sm[OFF_LN2B + 8 * q + 4]);
        float o[8];
        o[0] = fmaxf(0.f, fmaf((v[0] - mean) * rstd, lwa.x, lba.x));
        o[1] = fmaxf(0.f, fmaf((v[1] - mean) * rstd, lwa.y, lba.y));
        o[2] = fmaxf(0.f, fmaf((v[2] - mean) * rstd, lwa.z, lba.z));
        o[3] = fmaxf(0.f, fmaf((v[3] - mean) * rstd, lwa.w, lba.w));
        o[4] = fmaxf(0.f, fmaf((v[4] - mean) * rstd, lwb.x, lbb.x));
        o[5] = fmaxf(0.f, fmaf((v[5] - mean) * rstd, lwb.y, lbb.y));
        o[6] = fmaxf(0.f, fmaf((v[6] - mean) * rstd, lwb.z, lbb.z));
        o[7] = fmaxf(0.f, fmaf((v[7] - mean) * rstd, lwb.w, lbb.w));
#pragma unroll
        for (int i = 0; i < 8; i++)
            sm[OFF_HOUT + c * 33 + 8 * q + i] = o[i];
    }
    __syncwarp();

    // ---- phase 4: gate MLP -> logits -> clip -> mask -> exp ----
    {
        const float* hrow = &sm[OFF_HOUT + c * 33];
        float g1v[4];
#pragma unroll
        for (int e = 0; e < 4; e++) g1v[e] = sm[OFF_GB1 + 4 * q + e];
#pragma unroll
        for (int d = 0; d < 32; d++) {
            const float hvv = hrow[d];
            const float4 gw = *reinterpret_cast<const float4*>(&sm[OFF_GW1 + d * 16 + 4 * q]);
            g1v[0] = fmaf(hvv, gw.x, g1v[0]);
            g1v[1] = fmaf(hvv, gw.y, g1v[1]);
            g1v[2] = fmaf(hvv, gw.z, g1v[2]);
            g1v[3] = fmaf(hvv, gw.w, g1v[3]);
        }
        float pl[4] = {0.f, 0.f, 0.f, 0.f};
#pragma unroll
        for (int e = 0; e < 4; e++) {
            const float gv = fmaxf(0.f, g1v[e]);
            const float4 g2 = *reinterpret_cast<const float4*>(&sm[OFF_GW2 + (4 * q + e) * 4]);
            pl[0] = fmaf(gv, g2.x, pl[0]);
            pl[1] = fmaf(gv, g2.y, pl[1]);
            pl[2] = fmaf(gv, g2.z, pl[2]);
            pl[3] = fmaf(gv, g2.w, pl[3]);
        }
#pragma unroll
        for (int k = 0; k < 4; k++) {
            pl[k] += __shfl_xor_sync(0xffffffffu, pl[k], 1);
            pl[k] += __shfl_xor_sync(0xffffffffu, pl[k], 2);
        }
        const int mval = smi[OFF_MS + c];
        const float raw = pl[q] + sm[OFF_GB2 + q];
        const float lgt = fminf(10.f, fmaxf(-10.f, raw));
        const float ev  = (mval > 0) ? __expf(lgt) : 0.f;
        sm[OFF_ELOG + c * 4 + q] = ev;
        float se = ev;
        se += __shfl_xor_sync(0xffffffffu, se, 4);
        se += __shfl_xor_sync(0xffffffffu, se, 8);
        se += __shfl_xor_sync(0xffffffffu, se, 16);
        if (lane < 4) atomicAdd(&sm[OFF_SUME + lane], se);
        const unsigned bal = __ballot_sync(0xffffffffu, (q == 0) && (mval > 0));
        if (lane == 0) atomicAdd(&smi[OFF_MCNT], (int)__popc(bal));
    }
    __syncwarp();

    // ---- phase 5: pooling partials. thread (w,lane): rows 8w..8w+7, d=lane ----
    {
        float p0 = 0.f, p1 = 0.f, p2 = 0.f, p3 = 0.f;
#pragma unroll
        for (int rr = 0; rr < 8; rr++) {
            const float4 ev = *reinterpret_cast<const float4*>(&sm[OFF_ELOG + (r0 + rr) * 4]);
            const float h = sm[OFF_HOUT + (r0 + rr) * 33 + lane];
            p0 = fmaf(ev.x, h, p0);
            p1 = fmaf(ev.y, h, p1);
            p2 = fmaf(ev.z, h, p2);
            p3 = fmaf(ev.w, h, p3);
        }
        atomicAdd(&sm[OFF_NUMS + 0 * 32 + lane], p0);
        atomicAdd(&sm[OFF_NUMS + 1 * 32 + lane], p1);
        atomicAdd(&sm[OFF_NUMS + 2 * 32 + lane], p2);
        atomicAdd(&sm[OFF_NUMS + 3 * 32 + lane], p3);
    }
    __syncthreads();

    // ---- phase 6: flush tile accumulators ----
    if (t < 128)       atomicAdd(&g_num[b * 128 + t], sm[OFF_NUMS + t]);
    else if (t < 132)  atomicAdd(&g_sumexp[b * 4 + (t - 128)], sm[OFF_SUME + (t - 128)]);
    else if (t == 132) atomicAdd(&g_maskcnt[b], smi[OFF_MCNT]);
}

// ---------------------------------------------------------------------------
// Kernel C: per-batch tail (round-4 split-K version, 12.9us)
// ---------------------------------------------------------------------------
__global__ void k_tail(const float* __restrict__ c_w,    const float* __restrict__ c_b,
                       const float* __restrict__ c_ln_w, const float* __restrict__ c_ln_b,
                       const float* __restrict__ e_w1,   const float* __restrict__ e_b1,
                       const float* __restrict__ e_ln1_w, const float* __restrict__ e_ln1_b,
                       const float* __restrict__ e_w2,   const float* __restrict__ e_b2,
                       const float* __restrict__ e_ln2_w, const float* __restrict__ e_ln2_b,
                       float* __restrict__ out) {
    const int b = blockIdx.x;
    const int t = threadIdx.x;      // 256
    __shared__ float hs[128];
    __shared__ float comb[32];
    __shared__ float h2s[256];
    __shared__ float red[16];
    __shared__ float part[256];

    const int mc = g_maskcnt[b];
    if (t < 128) {
        const float den = g_sumexp[b * 4 + (t >> 5)];
        hs[t] = (mc > 0) ? g_num[b * 128 + t] / den : 0.f;
    }
    __syncthreads();

    // comb = relu(LN(hs @ c_w + c_b)); split K=128 across 8 groups
    {
        const int o = t & 31, kg = t >> 5;
        float a = 0.f;
#pragma unroll
        for (int k = 0; k < 16; k++)
            a = fmaf(hs[kg * 16 + k], c_w[(kg * 16 + k) * 32 + o], a);
        part[kg * 32 + o] = a;
    }
    __syncthreads();
    if (t < 32) {
        float a = c_b[t];
#pragma unroll
        for (int g = 0; g < 8; g++) a += part[g * 32 + t];
        float s1 = a, s2 = a * a;
#pragma unroll
        for (int m = 16; m > 0; m >>= 1) {
            s1 += __shfl_xor_sync(0xffffffffu, s1, m);
            s2 += __shfl_xor_sync(0xffffffffu, s2, m);
        }
        const float mean = s1 * (1.f / 32.f);
        const float var  = s2 * (1.f / 32.f) - mean * mean;
        const float r = rsqrtf(var + 1e-5f);
        const float v = fmaxf(0.f, fmaf((a - mean) * r, c_ln_w[t], c_ln_b[t]));
        comb[t] = (mc > 0) ? v : 0.f;
    }
    __syncthreads();

    // h = relu(LN(comb @ e_w1 + e_b1))   (256-wide block LN)
    {
        float a = e_b1[t];
#pragma unroll
        for (int k = 0; k < 32; k++) a = fmaf(comb[k], e_w1[k * 256 + t], a);
        float s1 = a, s2 = a * a;
#pragma unroll
        for (int m = 16; m > 0; m >>= 1) {
            s1 += __shfl_xor_sync(0xffffffffu, s1, m);
            s2 += __shfl_xor_sync(0xffffffffu, s2, m);
        }
        if ((t & 31) == 0) { red[t >> 5] = s1; red[8 + (t >> 5)] = s2; }
        __syncthreads();
        float S = 0.f, SS = 0.f;
#pragma unroll
        for (int i = 0; i < 8; i++) { S += red[i]; SS += red[8 + i]; }
        const float mean = S * (1.f / 256.f);
        const float var  = SS * (1.f / 256.f) - mean * mean;
        const float r = rsqrtf(var + 1e-5f);
        h2s[t] = fmaxf(0.f, fmaf((a - mean) * r, e_ln1_w[t], e_ln1_b[t]));
    }
    __syncthreads();

    // o = relu(LN(h @ e_w2 + e_b2)); split K=256 across 4 groups
    {
        const int o = t & 63, kg = t >> 6;
        float a = 0.f;
#pragma unroll 8
        for (int k = 0; k < 64; k++)
            a = fmaf(h2s[kg * 64 + k], e_w2[(kg * 64 + k) * 64 + o], a);
        part[kg * 64 + o] = a;
    }
    __syncthreads();
    float oacc = 0.f;
    if (t < 64) {
        oacc = e_b2[t] + part[t] + part[64 + t] + part[128 + t] + part[192 + t];
        float s1 = oacc, s2 = oacc * oacc;
#pragma unroll
        for (int m = 16; m > 0; m >>= 1) {
            s1 += __shfl_xor_sync(0xffffffffu, s1, m);
            s2 += __shfl_xor_sync(0xffffffffu, s2, m);
        }
        if ((t & 31) == 0) { red[t >> 5] = s1; red[8 + (t >> 5)] = s2; }
    }
    __syncthreads();
    if (t < 64) {
        const float S  = red[0] + red[1];
        const float SS = red[8] + red[9];
        const float mean = S * (1.f / 64.f);
        const float var  = SS * (1.f / 64.f) - mean * mean;
        const float r = rsqrtf(var + 1e-5f);
        const float o = fmaxf(0.f, fmaf((oacc - mean) * r, e_ln2_w[t], e_ln2_b[t]));
        out[(t >> 5) * (BB * 32) + b * 32 + (t & 31)] = o;
    }
}

// ---------------------------------------------------------------------------
// Launch
// ---------------------------------------------------------------------------
extern "C" void kernel_launch(void* const* d_in, const int* in_sizes, int n_in,
                              void* d_out, int out_size) {
    const float* x       = (const float*)d_in[0];
    const int*   mask    = (const int*)  d_in[1];
    const float* fe      = (const float*)d_in[2];
    const float* h_w1    = (const float*)d_in[3];
    const float* h_b1    = (const float*)d_in[4];
    const float* h_ln1_w = (const float*)d_in[5];
    const float* h_ln1_b = (const float*)d_in[6];
    const float* h_w2    = (const float*)d_in[7];
    const float* h_b2    = (const float*)d_in[8];
    const float* h_ln2_w = (const float*)d_in[9];
    const float* h_ln2_b = (const float*)d_in[10];
    const float* g_w1    = (const float*)d_in[11];
    const float* g_b1    = (const float*)d_in[12];
    const float* g_w2    = (const float*)d_in[13];
    const float* g_b2    = (const float*)d_in[14];
    const float* c_w     = (const float*)d_in[15];
    const float* c_b     = (const float*)d_in[16];
    const float* c_ln_w  = (const float*)d_in[17];
    const float* c_ln_b  = (const float*)d_in[18];
    const float* e_w1    = (const float*)d_in[19];
    const float* e_b1    = (const float*)d_in[20];
    const float* e_ln1_w = (const float*)d_in[21];
    const float* e_ln1_b = (const float*)d_in[22];
    const float* e_w2    = (const float*)d_in[23];
    const float* e_b2    = (const float*)d_in[24];
    const float* e_ln2_w = (const float*)d_in[25];
    const float* e_ln2_b = (const float*)d_in[26];
    float* out = (float*)d_out;

    cudaFuncSetAttribute(k_main, cudaFuncAttributeMaxDynamicSharedMemorySize, SMEM_BYTES);

    k_zero<<<64, 256>>>();
    k_fej<<<JJ, HH>>>(fe, h_w1, h_b1);
    dim3 grid(JJ / TJ, BB);
    k_main<<<grid, NT, SMEM_BYTES>>>(x, mask, h_w1, h_ln1_w, h_ln1_b,
                                     h_w2, h_b2, h_ln2_w, h_ln2_b,
                                     g_w1, g_b1, g_w2, g_b2);
    k_tail<<<BB, 256>>>(c_w, c_b, c_ln_w, c_ln_b,
                        e_w1, e_b1, e_ln1_w, e_ln1_b,
                        e_w2, e_b2, e_ln2_w, e_ln2_b, out);
}

// round 6
// speedup vs baseline: 1.6882x; 1.2818x over previous
#include <cuda_runtime.h>
#include <cuda_bf16.h>

// ---------------------------------------------------------------------------
// Problem constants
// ---------------------------------------------------------------------------
#define BB 128
#define JJ 8192
#define DD 32
#define HH 128

#define TJ 64       // cells per tile
#define NT 256      // threads per CTA
#define NTILES (BB * (JJ / TJ))   // 16384
#define GRID_MAIN 456             // ~3 CTAs per SM, persistent

// ---------------------------------------------------------------------------
// Scratch (device globals; no allocations allowed)
// ---------------------------------------------------------------------------
// g_fej layout (PERMUTED for coalesced phase-1 loads):
//   float index = (j>>3)*1024 + ((h>>2)&7)*128 + (j&7)*16 + (h>>5)*4 + (h&3)
// so that warp-instruction i of warp w reads 512B contiguous.
__device__ float g_fej[JJ * HH];          // 4 MB
__device__ float g_num[BB * 4 * DD];      // sum_j e_{jw} * h_out_{jd}
__device__ float g_sumexp[BB * 4];        // sum_j e_{jw}
__device__ int   g_maskcnt[BB];           // # observed junctions per batch

// ---------------------------------------------------------------------------
// Shared-memory layout (offsets in floats)
// ---------------------------------------------------------------------------
#define OFF_H1S   0
#define OFF_W2T   (OFF_H1S + TJ*132)          // 8448
#define OFF_HOUT  (OFF_W2T + 32*132)          // 12672  [64][33]
#define OFF_W10   (OFF_HOUT + TJ*33)          // 14784
#define OFF_LN1W  (OFF_W10 + 128)             // 14912
#define OFF_LN1B  (OFF_LN1W + 128)            // 15040
#define OFF_LN2W  (OFF_LN1B + 128)            // 15168
#define OFF_LN2B  (OFF_LN2W + 32)             // 15200
#define OFF_HB2   (OFF_LN2B + 32)             // 15232
#define OFF_GW1   (OFF_HB2 + 32)              // 15264 : [32][16]
#define OFF_GB1   (OFF_GW1 + 512)             // 15776
#define OFF_GW2   (OFF_GB1 + 16)              // 15792 : [16][4]
#define OFF_GB2   (OFF_GW2 + 64)              // 15856
#define OFF_XS    (OFF_GB2 + 4)               // 15860
#define OFF_ELOG  (OFF_XS + 64)               // 15924 (16B aligned)
#define OFF_MS    (OFF_ELOG + 256)            // 16180 (ints)
#define SMEM_BYTES 65536
// Per-warp pooling partials overlay the warp's OWN dead h1s rows (8w..8w+7):
//   WNUMS(w,head,d) = OFF_H1S + (8w)*132 + head*32 + d     (row 8w, cols 0..127)
//   WSUME(w,q)      = OFF_H1S + (8w)*132 + 128 + q         (row 8w padding)
//   WCNT(w)         = OFF_H1S + (8w+1)*132 + 128           (row 8w+1 padding, int)

// packed fp32x2 FMA:  c = a*b + c
#define FMA2(c_, a_, b_) \
    asm("fma.rn.f32x2 %0, %1, %2, %0;" : "+l"(c_) : "l"(a_), "l"(b_))

// ---------------------------------------------------------------------------
// Kernel Z: zero per-launch global accumulators
// ---------------------------------------------------------------------------
__global__ void k_zero() {
    int i = blockIdx.x * 256 + threadIdx.x;
    if (i < BB * 4 * DD) g_num[i] = 0.f;
    if (i < BB * 4)      g_sumexp[i] = 0.f;
    if (i < BB)          g_maskcnt[i] = 0;
}

// ---------------------------------------------------------------------------
// Kernel A: build permuted g_fej. One block per 8 j's; thread t writes
// float4 #t of the block's 1024-float window (fully coalesced stores).
//   f = 4t = i*128 + jc*16 + qq*4  ->  j = j8*8+jc, h = 32*qq + 4*i + comp
// ---------------------------------------------------------------------------
__global__ void k_fej(const float* __restrict__ fe,
                      const float* __restrict__ h_w1,
                      const float* __restrict__ h_b1) {
    __shared__ float fes[8][33];
    const int j8 = blockIdx.x;
    const int t  = threadIdx.x;          // 256
    fes[t >> 5][t & 31] = fe[(j8 * 8 + (t >> 5)) * DD + (t & 31)];
    __syncthreads();
    const int f  = 4 * t;
    const int i  = f >> 7;
    const int jc = (f >> 4) & 7;
    const int qq = (f >> 2) & 3;
    const int h0 = 32 * qq + 4 * i;
    float4 acc = *reinterpret_cast<const float4*>(&h_b1[h0]);
    const float* fr = fes[jc];
#pragma unroll 8
    for (int d = 0; d < 32; d++) {
        const float4 wv = *reinterpret_cast<const float4*>(&h_w1[(1 + d) * HH + h0]);
        const float fv = fr[d];
        acc.x = fmaf(fv, wv.x, acc.x);
        acc.y = fmaf(fv, wv.y, acc.y);
        acc.z = fmaf(fv, wv.z, acc.z);
        acc.w = fmaf(fv, wv.w, acc.w);
    }
    *reinterpret_cast<float4*>(&g_fej[j8 * 1024 + f]) = acc;
}

// ---------------------------------------------------------------------------
// Kernel B: persistent fused per-cell pipeline. Each CTA stages weights once,
// then loops over (b, j-tile) work items.
// ---------------------------------------------------------------------------
__global__ void __launch_bounds__(NT, 3)
k_main(const float* __restrict__ x, const int* __restrict__ mask,
       const float* __restrict__ h_w1,
       const float* __restrict__ h_ln1_w, const float* __restrict__ h_ln1_b,
       const float* __restrict__ h_w2,   const float* __restrict__ h_b2,
       const float* __restrict__ h_ln2_w, const float* __restrict__ h_ln2_b,
       const float* __restrict__ gw1,    const float* __restrict__ gb1,
       const float* __restrict__ gw2,    const float* __restrict__ gb2) {
    extern __shared__ float sm[];
    int* smi = (int*)sm;
    const int t  = threadIdx.x;
    const int c = t >> 2, q = t & 3;
    const int w = t >> 5, lane = t & 31, r0 = w * 8;

    // ---- one-time weight staging ----
    for (int i = t; i < HH * DD; i += NT) {           // h_w2 -> transposed [d][132]
        int k = i >> 5, d = i & 31;
        sm[OFF_W2T + d * 132 + k] = h_w2[i];
    }
    if (t < HH) {
        sm[OFF_W10 + t]  = h_w1[t];
        sm[OFF_LN1W + t] = h_ln1_w[t];
        sm[OFF_LN1B + t] = h_ln1_b[t];
    }
    if (t < DD) {
        sm[OFF_LN2W + t] = h_ln2_w[t];
        sm[OFF_LN2B + t] = h_ln2_b[t];
        sm[OFF_HB2 + t]  = h_b2[t];
    }
    for (int i = t; i < 512; i += NT) sm[OFF_GW1 + i] = gw1[i];
    if (t < 16) sm[OFF_GB1 + t] = gb1[t];
    if (t < 64) sm[OFF_GW2 + t] = gw2[t];
    if (t < 4)  sm[OFF_GB2 + t] = gb2[t];

    const float4* fj4 = reinterpret_cast<const float4*>(g_fej);

    for (int tile = blockIdx.x; tile < NTILES; tile += GRID_MAIN) {
        const int b  = tile >> 7;
        const int j0 = (tile & 127) * TJ;

        __syncthreads();   // smem reuse fence (prev iter reads done)
        if (t < TJ) {
            sm[OFF_XS + t]  = x[b * JJ + j0 + t];
            smi[OFF_MS + t] = mask[b * JJ + j0 + t];
        }
        __syncthreads();

        // ---- phase 1: pre = x*w1_0 + fej ; LN(128) ; relu ; -> h1s ----
        {
            const int fbase = ((j0 + c) >> 3) * 256 + (c & 7) * 4 + q;
            const float xv = sm[OFF_XS + c];
            float4 pv[8];
            float s = 0.f, ss = 0.f;
#pragma unroll
            for (int i = 0; i < 8; i++) {
                float4 f = fj4[fbase + 32 * i];
                const float4 wv = *reinterpret_cast<const float4*>(&sm[OFF_W10 + q * 32 + 4 * i]);
                float4 v;
                v.x = fmaf(xv, wv.x, f.x);
                v.y = fmaf(xv, wv.y, f.y);
                v.z = fmaf(xv, wv.z, f.z);
                v.w = fmaf(xv, wv.w, f.w);
                pv[i] = v;
                s  += (v.x + v.y) + (v.z + v.w);
                ss += v.x * v.x + v.y * v.y + v.z * v.z + v.w * v.w;
            }
            s  += __shfl_xor_sync(0xffffffffu, s, 1);
            s  += __shfl_xor_sync(0xffffffffu, s, 2);
            ss += __shfl_xor_sync(0xffffffffu, ss, 1);
            ss += __shfl_xor_sync(0xffffffffu, ss, 2);
            const float mean = s * (1.f / 128.f);
            const float var  = ss * (1.f / 128.f) - mean * mean;
            const float rstd = rsqrtf(var + 1e-5f);
#pragma unroll
            for (int sstep = 0; sstep < 8; sstep++) {
                const int i = (sstep + 2 * q) & 7;   // conflict-free STS.128
                float4 v = pv[i];
                const float4 lw = *reinterpret_cast<const float4*>(&sm[OFF_LN1W + q * 32 + 4 * i]);
                const float4 lb = *reinterpret_cast<const float4*>(&sm[OFF_LN1B + q * 32 + 4 * i]);
                float4 o;
                o.x = fmaxf(0.f, fmaf((v.x - mean) * rstd, lw.x, lb.x));
                o.y = fmaxf(0.f, fmaf((v.y - mean) * rstd, lw.y, lb.y));
                o.z = fmaxf(0.f, fmaf((v.z - mean) * rstd, lw.z, lb.z));
                o.w = fmaxf(0.f, fmaf((v.w - mean) * rstd, lw.w, lb.w));
                *reinterpret_cast<float4*>(&sm[OFF_H1S + c * 132 + q * 32 + 4 * i]) = o;
            }
        }
        __syncwarp();   // h1s rows 8w..8w+7 produced & consumed by warp w only

        // ---- phase 2: GEMM h1[64x128] @ w2[128x32], f32x2-packed ----
        float hv[8];
        {
            unsigned long long acc2[8] = {0ull,0ull,0ull,0ull,0ull,0ull,0ull,0ull};
            const float* wrow   = &sm[OFF_W2T + lane * 132];
            const float* h1base = &sm[OFF_H1S + r0 * 132];
#pragma unroll 4
            for (int k4 = 0; k4 < 32; k4++) {
                const ulonglong2 bv = *reinterpret_cast<const ulonglong2*>(wrow + 4 * k4);
#pragma unroll
                for (int rr = 0; rr < 8; rr++) {
                    const ulonglong2 av = *reinterpret_cast<const ulonglong2*>(h1base + rr * 132 + 4 * k4);
                    FMA2(acc2[rr], av.x, bv.x);
                    FMA2(acc2[rr], av.y, bv.y);
                }
            }
#pragma unroll
            for (int rr = 0; rr < 8; rr++) {
                unsigned lo, hi;
                asm("mov.b64 {%0,%1}, %2;" : "=r"(lo), "=r"(hi) : "l"(acc2[rr]));
                hv[rr] = __uint_as_float(lo) + __uint_as_float(hi);
            }
        }

        // ---- phase 3a: store pre-LN rows (v = acc + b2) to hout ----
        {
            const float bb2 = sm[OFF_HB2 + lane];
#pragma unroll
            for (int rr = 0; rr < 8; rr++)
                sm[OFF_HOUT + (r0 + rr) * 33 + lane] = hv[rr] + bb2;
        }
        __syncwarp();

        // ---- phase 3b: LN over D=32 per row (4 shfls) ----
        {
            float v[8];
            float s1 = 0.f, s2 = 0.f;
#pragma unroll
            for (int i = 0; i < 8; i++) {
                v[i] = sm[OFF_HOUT + c * 33 + 8 * q + i];
                s1 += v[i];
                s2 = fmaf(v[i], v[i], s2);
            }
            s1 += __shfl_xor_sync(0xffffffffu, s1, 1);
            s1 += __shfl_xor_sync(0xffffffffu, s1, 2);
            s2 += __shfl_xor_sync(0xffffffffu, s2, 1);
            s2 += __shfl_xor_sync(0xffffffffu, s2, 2);
            const float mean = s1 * (1.f / 32.f);
            const float var  = s2 * (1.f / 32.f) - mean * mean;
            const float rstd = rsqrtf(var + 1e-5f);
            const float4 lwa = *reinterpret_cast<const float4*>(&sm[OFF_LN2W + 8 * q]);
            const float4 lwb = *reinterpret_cast<const float4*>(&sm[OFF_LN2W + 8 * q + 4]);
            const float4 lba = *reinterpret_cast<const float4*>(&sm[OFF_LN2B + 8 * q]);
            const float4 lbb = *reinterpret_cast<const float4*>(&sm[OFF_LN2B + 8 * q + 4]);
            float o[8];
            o[0] = fmaxf(0.f, fmaf((v[0] - mean) * rstd, lwa.x, lba.x));
            o[1] = fmaxf(0.f, fmaf((v[1] - mean) * rstd, lwa.y, lba.y));
            o[2] = fmaxf(0.f, fmaf((v[2] - mean) * rstd, lwa.z, lba.z));
            o[3] = fmaxf(0.f, fmaf((v[3] - mean) * rstd, lwa.w, lba.w));
            o[4] = fmaxf(0.f, fmaf((v[4] - mean) * rstd, lwb.x, lbb.x));
            o[5] = fmaxf(0.f, fmaf((v[5] - mean) * rstd, lwb.y, lbb.y));
            o[6] = fmaxf(0.f, fmaf((v[6] - mean) * rstd, lwb.z, lbb.z));
            o[7] = fmaxf(0.f, fmaf((v[7] - mean) * rstd, lwb.w, lbb.w));
#pragma unroll
            for (int i = 0; i < 8; i++)
                sm[OFF_HOUT + c * 33 + 8 * q + i] = o[i];
        }
        __syncwarp();

        // ---- phase 4: gate MLP -> logits -> clip -> mask -> exp ----
        float se;            // lanes 0-3: per-warp sum_exp for head=lane
        int   cnt;           // lane 0:   per-warp observed count
        {
            const float* hrow = &sm[OFF_HOUT + c * 33];
            float g1v[4];
#pragma unroll
            for (int e = 0; e < 4; e++) g1v[e] = sm[OFF_GB1 + 4 * q + e];
#pragma unroll
            for (int d = 0; d < 32; d++) {
                const float hvv = hrow[d];
                const float4 gw = *reinterpret_cast<const float4*>(&sm[OFF_GW1 + d * 16 + 4 * q]);
                g1v[0] = fmaf(hvv, gw.x, g1v[0]);
                g1v[1] = fmaf(hvv, gw.y, g1v[1]);
                g1v[2] = fmaf(hvv, gw.z, g1v[2]);
                g1v[3] = fmaf(hvv, gw.w, g1v[3]);
            }
            float pl[4] = {0.f, 0.f, 0.f, 0.f};
#pragma unroll
            for (int e = 0; e < 4; e++) {
                const float gv = fmaxf(0.f, g1v[e]);
                const float4 g2 = *reinterpret_cast<const float4*>(&sm[OFF_GW2 + (4 * q + e) * 4]);
                pl[0] = fmaf(gv, g2.x, pl[0]);
                pl[1] = fmaf(gv, g2.y, pl[1]);
                pl[2] = fmaf(gv, g2.z, pl[2]);
                pl[3] = fmaf(gv, g2.w, pl[3]);
            }
#pragma unroll
            for (int k = 0; k < 4; k++) {
                pl[k] += __shfl_xor_sync(0xffffffffu, pl[k], 1);
                pl[k] += __shfl_xor_sync(0xffffffffu, pl[k], 2);
            }
            const int mval = smi[OFF_MS + c];
            const float raw = pl[q] + sm[OFF_GB2 + q];
            const float lgt = fminf(10.f, fmaxf(-10.f, raw));
            const float ev  = (mval > 0) ? __expf(lgt) : 0.f;
            sm[OFF_ELOG + c * 4 + q] = ev;
            se = ev;
            se += __shfl_xor_sync(0xffffffffu, se, 4);
            se += __shfl_xor_sync(0xffffffffu, se, 8);
            se += __shfl_xor_sync(0xffffffffu, se, 16);
            const unsigned bal = __ballot_sync(0xffffffffu, (q == 0) && (mval > 0));
            cnt = (int)__popc(bal);
        }
        __syncwarp();

        // ---- phase 5: pooling partials into warp-own dead h1s rows ----
        {
            float p0 = 0.f, p1 = 0.f, p2 = 0.f, p3 = 0.f;
#pragma unroll
            for (int rr = 0; rr < 8; rr++) {
                const float4 ev = *reinterpret_cast<const float4*>(&sm[OFF_ELOG + (r0 + rr) * 4]);
                const float h = sm[OFF_HOUT + (r0 + rr) * 33 + lane];
                p0 = fmaf(ev.x, h, p0);
                p1 = fmaf(ev.y, h, p1);
                p2 = fmaf(ev.z, h, p2);
                p3 = fmaf(ev.w, h, p3);
            }
            float* wn = &sm[OFF_H1S + r0 * 132];   // warp-own row 8w
            wn[0 * 32 + lane] = p0;
            wn[1 * 32 + lane] = p1;
            wn[2 * 32 + lane] = p2;
            wn[3 * 32 + lane] = p3;
            if (lane < 4) wn[128 + lane] = se;                     // WSUME
            if (lane == 0) smi[OFF_H1S + (r0 + 1) * 132 + 128] = cnt; // WCNT
        }
        __syncthreads();

        // ---- phase 6: cross-warp reduce + global RED ----
        if (t < 128) {
            float a = 0.f;
#pragma unroll
            for (int ww = 0; ww < 8; ww++) a += sm[OFF_H1S + (8 * ww) * 132 + t];
            atomicAdd(&g_num[b * 128 + t], a);
        } else if (t < 132) {
            const int hq = t - 128;
            float a = 0.f;
#pragma unroll
            for (int ww = 0; ww < 8; ww++) a += sm[OFF_H1S + (8 * ww) * 132 + 128 + hq];
            atomicAdd(&g_sumexp[b * 4 + hq], a);
        } else if (t == 132) {
            int a = 0;
#pragma unroll
            for (int ww = 0; ww < 8; ww++) a += smi[OFF_H1S + (8 * ww + 1) * 132 + 128];
            atomicAdd(&g_maskcnt[b], a);
        }
    }
}

// ---------------------------------------------------------------------------
// Kernel C: per-batch tail  head_sums -> comb -> e1 -> e2 -> (mu, logvar)
// ---------------------------------------------------------------------------
__global__ void k_tail(const float* __restrict__ c_w,    const float* __restrict__ c_b,
                       const float* __restrict__ c_ln_w, const float* __restrict__ c_ln_b,
                       const float* __restrict__ e_w1,   const float* __restrict__ e_b1,
                       const float* __restrict__ e_ln1_w, const float* __restrict__ e_ln1_b,
                       const float* __restrict__ e_w2,   const float* __restrict__ e_b2,
                       const float* __restrict__ e_ln2_w, const float* __restrict__ e_ln2_b,
                       float* __restrict__ out) {
    const int b = blockIdx.x;
    const int t = threadIdx.x;      // 256
    __shared__ float hs[128];
    __shared__ float comb[32];
    __shared__ float h2s[256];
    __shared__ float red[16];
    __shared__ float part[256];

    const int mc = g_maskcnt[b];
    if (t < 128) {
        const float den = g_sumexp[b * 4 + (t >> 5)];
        hs[t] = (mc > 0) ? g_num[b * 128 + t] / den : 0.f;
    }
    __syncthreads();

    // comb = relu(LN(hs @ c_w + c_b)); split K=128 across 8 groups
    {
        const int o = t & 31, kg = t >> 5;
        float a = 0.f;
#pragma unroll
        for (int k = 0; k < 16; k++)
            a = fmaf(hs[kg * 16 + k], c_w[(kg * 16 + k) * 32 + o], a);
        part[kg * 32 + o] = a;
    }
    __syncthreads();
    if (t < 32) {
        float a = c_b[t];
#pragma unroll
        for (int g = 0; g < 8; g++) a += part[g * 32 + t];
        float s1 = a, s2 = a * a;
#pragma unroll
        for (int m = 16; m > 0; m >>= 1) {
            s1 += __shfl_xor_sync(0xffffffffu, s1, m);
            s2 += __shfl_xor_sync(0xffffffffu, s2, m);
        }
        const float mean = s1 * (1.f / 32.f);
        const float var  = s2 * (1.f / 32.f) - mean * mean;
        const float r = rsqrtf(var + 1e-5f);
        const float v = fmaxf(0.f, fmaf((a - mean) * r, c_ln_w[t], c_ln_b[t]));
        comb[t] = (mc > 0) ? v : 0.f;
    }
    __syncthreads();

    // h = relu(LN(comb @ e_w1 + e_b1))   (256-wide block LN)
    {
        float a = e_b1[t];
#pragma unroll
        for (int k = 0; k < 32; k++) a = fmaf(comb[k], e_w1[k * 256 + t], a);
        float s1 = a, s2 = a * a;
#pragma unroll
        for (int m = 16; m > 0; m >>= 1) {
            s1 += __shfl_xor_sync(0xffffffffu, s1, m);
            s2 += __shfl_xor_sync(0xffffffffu, s2, m);
        }
        if ((t & 31) == 0) { red[t >> 5] = s1; red[8 + (t >> 5)] = s2; }
        __syncthreads();
        float S = 0.f, SS = 0.f;
#pragma unroll
        for (int i = 0; i < 8; i++) { S += red[i]; SS += red[8 + i]; }
        const float mean = S * (1.f / 256.f);
        const float var  = SS * (1.f / 256.f) - mean * mean;
        const float r = rsqrtf(var + 1e-5f);
        h2s[t] = fmaxf(0.f, fmaf((a - mean) * r, e_ln1_w[t], e_ln1_b[t]));
    }
    __syncthreads();

    // o = relu(LN(h @ e_w2 + e_b2)); split K=256 across 4 groups
    {
        const int o = t & 63, kg = t >> 6;
        float a = 0.f;
#pragma unroll 8
        for (int k = 0; k < 64; k++)
            a = fmaf(h2s[kg * 64 + k], e_w2[(kg * 64 + k) * 64 + o], a);
        part[kg * 64 + o] = a;
    }
    __syncthreads();
    float oacc = 0.f;
    if (t < 64) {
        oacc = e_b2[t] + part[t] + part[64 + t] + part[128 + t] + part[192 + t];
        float s1 = oacc, s2 = oacc * oacc;
#pragma unroll
        for (int m = 16; m > 0; m >>= 1) {
            s1 += __shfl_xor_sync(0xffffffffu, s1, m);
            s2 += __shfl_xor_sync(0xffffffffu, s2, m);
        }
        if ((t & 31) == 0) { red[t >> 5] = s1; red[8 + (t >> 5)] = s2; }
    }
    __syncthreads();
    if (t < 64) {
        const float S  = red[0] + red[1];
        const float SS = red[8] + red[9];
        const float mean = S * (1.f / 64.f);
        const float var  = SS * (1.f / 64.f) - mean * mean;
        const float r = rsqrtf(var + 1e-5f);
        const float o = fmaxf(0.f, fmaf((oacc - mean) * r, e_ln2_w[t], e_ln2_b[t]));
        out[(t >> 5) * (BB * 32) + b * 32 + (t & 31)] = o;
    }
}

// ---------------------------------------------------------------------------
// Launch
// ---------------------------------------------------------------------------
extern "C" void kernel_launch(void* const* d_in, const int* in_sizes, int n_in,
                              void* d_out, int out_size) {
    const float* x       = (const float*)d_in[0];
    const int*   mask    = (const int*)  d_in[1];
    const float* fe      = (const float*)d_in[2];
    const float* h_w1    = (const float*)d_in[3];
    const float* h_b1    = (const float*)d_in[4];
    const float* h_ln1_w = (const float*)d_in[5];
    const float* h_ln1_b = (const float*)d_in[6];
    const float* h_w2    = (const float*)d_in[7];
    const float* h_b2    = (const float*)d_in[8];
    const float* h_ln2_w = (const float*)d_in[9];
    const float* h_ln2_b = (const float*)d_in[10];
    const float* g_w1    = (const float*)d_in[11];
    const float* g_b1    = (const float*)d_in[12];
    const float* g_w2    = (const float*)d_in[13];
    const float* g_b2    = (const float*)d_in[14];
    const float* c_w     = (const float*)d_in[15];
    const float* c_b     = (const float*)d_in[16];
    const float* c_ln_w  = (const float*)d_in[17];
    const float* c_ln_b  = (const float*)d_in[18];
    const float* e_w1    = (const float*)d_in[19];
    const float* e_b1    = (const float*)d_in[20];
    const float* e_ln1_w = (const float*)d_in[21];
    const float* e_ln1_b = (const float*)d_in[22];
    const float* e_w2    = (const float*)d_in[23];
    const float* e_b2    = (const float*)d_in[24];
    const float* e_ln2_w = (const float*)d_in[25];
    const float* e_ln2_b = (const float*)d_in[26];
    float* out = (float*)d_out;

    cudaFuncSetAttribute(k_main, cudaFuncAttributeMaxDynamicSharedMemorySize, SMEM_BYTES);

    k_zero<<<64, 256>>>();
    k_fej<<<JJ / 8, 256>>>(fe, h_w1, h_b1);
    k_main<<<GRID_MAIN, NT, SMEM_BYTES>>>(x, mask, h_w1, h_ln1_w, h_ln1_b,
                                          h_w2, h_b2, h_ln2_w, h_ln2_b,
                                          g_w1, g_b1, g_w2, g_b2);
    k_tail<<<BB, 256>>>(c_w, c_b, c_ln_w, c_ln_b,
                        e_w1, e_b1, e_ln1_w, e_ln1_b,
                        e_w2, e_b2, e_ln2_w, e_ln2_b, out);
}